// round 2
// baseline (speedup 1.0000x reference)
#include <cuda_runtime.h>
#include <cstdint>

#define B_  2
#define N_  2048
#define D_  1024
#define H_  16
#define HD_ 64
#define S_  2048
#define BH_ (B_*H_)

typedef unsigned long long ull;

// ---- packed f32x2 helpers (bit-exact with scalar fmaf) ----------------------
__device__ __forceinline__ ull pk2(float lo, float hi) {
    ull r; asm("mov.b64 %0, {%1,%2};" : "=l"(r) : "f"(lo), "f"(hi)); return r;
}
__device__ __forceinline__ void fma2(ull& d, ull a, ull b) {
    asm("fma.rn.f32x2 %0, %1, %2, %0;" : "+l"(d) : "l"(a), "l"(b));
}
__device__ __forceinline__ float2 up2(ull v) {
    float2 r; asm("mov.b64 {%0,%1}, %2;" : "=f"(r.x), "=f"(r.y) : "l"(v)); return r;
}

// ---------------- scratch ----------------------------------------------------
static __device__ float g_q[(size_t)BH_*N_*HD_];     // [b,h,n,hd]
static __device__ float g_k[(size_t)BH_*N_*HD_];
static __device__ float g_v[(size_t)BH_*N_*HD_];
static __device__ float g_ao[(size_t)B_*N_*D_];      // attn_out [b,n,d]
static __device__ float g_rowsum[(size_t)BH_*N_];

// =============================================================================
// Kernel 1: QKV projection (f32x2 inner loop).
// C[m,n] = sum_k A[m,k]*W[n,k] + bias[n];  scatter into g_q/g_k/g_v.
// =============================================================================
__global__ void __launch_bounds__(256) qkv_gemm(const float* __restrict__ A,
                                                const float* __restrict__ W,
                                                const float* __restrict__ bias) {
    __shared__ float As2[8][264];   // A duplicated: value at col m stored at 2m,2m+1
    __shared__ float Bs[8][132];
    int tid = threadIdx.x;
    int tx = tid & 15, ty = tid >> 4;
    int m0 = blockIdx.y << 7, n0 = blockIdx.x << 7;

    ull accp[8][4];
#pragma unroll
    for (int i = 0; i < 8; i++)
#pragma unroll
        for (int j = 0; j < 4; j++) accp[i][j] = 0ULL;

    int lr = tid >> 1;            // 0..127
    int lc = (tid & 1) << 2;      // 0 or 4
    const float* Ap = A + (size_t)(m0 + lr) * 1024 + lc;
    const float* Wp = W + (size_t)(n0 + lr) * 1024 + lc;

    float4 av = *(const float4*)(Ap);
    float4 wv = *(const float4*)(Wp);

    for (int k0 = 0; k0 < 1024; k0 += 8) {
        __syncthreads();
        *(ull*)&As2[lc + 0][2 * lr] = pk2(av.x, av.x);
        *(ull*)&As2[lc + 1][2 * lr] = pk2(av.y, av.y);
        *(ull*)&As2[lc + 2][2 * lr] = pk2(av.z, av.z);
        *(ull*)&As2[lc + 3][2 * lr] = pk2(av.w, av.w);
        Bs[lc + 0][lr] = wv.x; Bs[lc + 1][lr] = wv.y;
        Bs[lc + 2][lr] = wv.z; Bs[lc + 3][lr] = wv.w;
        __syncthreads();
        if (k0 + 8 < 1024) {
            av = *(const float4*)(Ap + k0 + 8);
            wv = *(const float4*)(Wp + k0 + 8);
        }
#pragma unroll
        for (int kk = 0; kk < 8; kk++) {
            ull ap[8], bp[4];
#pragma unroll
            for (int u = 0; u < 4; u++) {
                ulonglong2 t = *(const ulonglong2*)&As2[kk][(ty << 4) + (u << 2)];
                ap[2 * u] = t.x; ap[2 * u + 1] = t.y;
            }
            {
                ulonglong2 t0 = *(const ulonglong2*)&Bs[kk][tx << 3];
                ulonglong2 t1 = *(const ulonglong2*)&Bs[kk][(tx << 3) + 4];
                bp[0] = t0.x; bp[1] = t0.y; bp[2] = t1.x; bp[3] = t1.y;
            }
#pragma unroll
            for (int i = 0; i < 8; i++)
#pragma unroll
                for (int j = 0; j < 4; j++)
                    fma2(accp[i][j], ap[i], bp[j]);
        }
    }

    int ncol = n0 + (tx << 3);
    int which = ncol >> 10;
    int rem = ncol & 1023;
    int h = rem >> 6, hd = rem & 63;
    float* dst = (which == 0) ? g_q : ((which == 1) ? g_k : g_v);
    float bv[8];
#pragma unroll
    for (int j = 0; j < 8; j++) bv[j] = bias[ncol + j];
#pragma unroll
    for (int i = 0; i < 8; i++) {
        int m = m0 + (ty << 3) + i;
        int bb = m >> 11, row = m & 2047;
        float* p = dst + (((size_t)(bb * H_ + h) * N_ + row) * HD_ + hd);
        float2 c0 = up2(accp[i][0]), c1 = up2(accp[i][1]);
        float2 c2 = up2(accp[i][2]), c3 = up2(accp[i][3]);
        *(float4*)p = make_float4(c0.x + bv[0], c0.y + bv[1], c1.x + bv[2], c1.y + bv[3]);
        *(float4*)(p + 4) = make_float4(c2.x + bv[4], c2.y + bv[5], c3.x + bv[6], c3.y + bv[7]);
    }
}

// =============================================================================
// Kernel 2: fused attention with f32x2 math.
// Q,K tiles stored transposed (hd-major) in smem; exp tile stored transposed
// (kk-major) so both GEMM loops pack along query-row pairs.
// =============================================================================
#define QS_OFF 0                         // qs_t[64][132]
#define KS_OFF (64*132)                  // ks_t[64][68]
#define VS_OFF (KS_OFF + 64*68)          // vs[64][64]
#define ES_OFF (VS_OFF + 64*64)          // es_t[64][132]
#define RC_OFF (ES_OFF + 64*132)         // rc[2048]
#define ATTN_SMEM ((RC_OFF + 2048) * 4)  // 109568 bytes

__global__ void __launch_bounds__(256, 2) attn_kernel(float* __restrict__ attn,
                                                      const float* __restrict__ rpe,
                                                      int write_attn) {
    extern __shared__ float sm[];
    float* qs = sm + QS_OFF;
    float* ks = sm + KS_OFF;
    float* vs = sm + VS_OFF;
    float* es = sm + ES_OFF;
    float* rc = sm + RC_OFF;

    int qt = blockIdx.x, h = blockIdx.y, b = blockIdx.z;
    int bh = b * H_ + h;
    int tid = threadIdx.x, tx = tid & 15, ty = tid >> 4;
    int q0 = qt << 7;

    for (int i = tid; i < S_; i += 256) rc[i] = rpe[(size_t)i * H_ + h];

    // load Q tile transposed: qs[hd][row]
    const float* qg = g_q + ((size_t)bh * N_ + q0) * HD_;
#pragma unroll
    for (int it = 0; it < 8; it++) {
        int f4 = tid + it * 256;               // 0..2047
        int row = f4 >> 4, c = (f4 & 15) << 2;
        float4 v = *(const float4*)(qg + row * 64 + c);
        qs[(c + 0) * 132 + row] = v.x;
        qs[(c + 1) * 132 + row] = v.y;
        qs[(c + 2) * 132 + row] = v.z;
        qs[(c + 3) * 132 + row] = v.w;
    }

    ull op[4][4];        // [i-pair][hd col] packed over adjacent query rows
    float rs[8];
#pragma unroll
    for (int p = 0; p < 4; p++)
#pragma unroll
        for (int j = 0; j < 4; j++) op[p][j] = 0ULL;
#pragma unroll
    for (int i = 0; i < 8; i++) rs[i] = 0.f;

    const float scale = 0.125f;   // HD^-0.5

    for (int t = 0; t < N_ / 64; t++) {
        __syncthreads();
        const float* kg = g_k + ((size_t)bh * N_ + t * 64) * HD_;
        const float* vg = g_v + ((size_t)bh * N_ + t * 64) * HD_;
#pragma unroll
        for (int it = 0; it < 4; it++) {
            int f4 = tid + it * 256;           // 0..1023
            int row = f4 >> 4, c = (f4 & 15) << 2;
            float4 kv = *(const float4*)(kg + row * 64 + c);
            ks[(c + 0) * 68 + row] = kv.x;
            ks[(c + 1) * 68 + row] = kv.y;
            ks[(c + 2) * 68 + row] = kv.z;
            ks[(c + 3) * 68 + row] = kv.w;
            *(float4*)(vs + row * 64 + c) = *(const float4*)(vg + row * 64 + c);
        }
        __syncthreads();

        // ---- QK^T: sp[4 i-pairs][4 j] ----
        ull sp[4][4];
#pragma unroll
        for (int p = 0; p < 4; p++)
#pragma unroll
            for (int j = 0; j < 4; j++) sp[p][j] = 0ULL;
#pragma unroll 8
        for (int hd = 0; hd < 64; hd++) {
            ull ap[4], bd[4];
            {
                ulonglong2 t0 = *(const ulonglong2*)&qs[hd * 132 + (ty << 3)];
                ulonglong2 t1 = *(const ulonglong2*)&qs[hd * 132 + (ty << 3) + 4];
                ap[0] = t0.x; ap[1] = t0.y; ap[2] = t1.x; ap[3] = t1.y;
            }
            float4 bv = *(const float4*)&ks[hd * 68 + (tx << 2)];
            bd[0] = pk2(bv.x, bv.x); bd[1] = pk2(bv.y, bv.y);
            bd[2] = pk2(bv.z, bv.z); bd[3] = pk2(bv.w, bv.w);
#pragma unroll
            for (int p = 0; p < 4; p++)
#pragma unroll
                for (int j = 0; j < 4; j++)
                    fma2(sp[p][j], ap[p], bd[j]);
        }

        // ---- unpack, bias + exp + rowsum + stores ----
        float s[8][4];
#pragma unroll
        for (int p = 0; p < 4; p++)
#pragma unroll
            for (int j = 0; j < 4; j++) {
                float2 v = up2(sp[p][j]);
                s[2 * p][j] = v.x; s[2 * p + 1][j] = v.y;
            }

        int k0 = t * 64;
#pragma unroll
        for (int i = 0; i < 8; i++) {
            int qi = q0 + (ty << 3) + i;
            float e4[4];
#pragma unroll
            for (int j = 0; j < 4; j++) {
                int kj = k0 + (tx << 2) + j;
                int d = qi - kj; if (d < 0) d = -d;
                float e = __expf(fmaf(s[i][j], scale, rc[d]));
                e4[j] = e;
                rs[i] += e;
                es[((tx << 2) + j) * 132 + (ty << 3) + i] = e;   // transposed
            }
            if (write_attn)
                *(float4*)&attn[((size_t)bh * N_ + qi) * N_ + k0 + (tx << 2)] =
                    make_float4(e4[0], e4[1], e4[2], e4[3]);
        }
        __syncthreads();

        // ---- AV: op[i-pair][hd] += e_t[kk][i] * v[kk][hd] ----
#pragma unroll 8
        for (int kk = 0; kk < 64; kk++) {
            ull ap[4], bd[4];
            {
                ulonglong2 t0 = *(const ulonglong2*)&es[kk * 132 + (ty << 3)];
                ulonglong2 t1 = *(const ulonglong2*)&es[kk * 132 + (ty << 3) + 4];
                ap[0] = t0.x; ap[1] = t0.y; ap[2] = t1.x; ap[3] = t1.y;
            }
            float4 bv = *(const float4*)&vs[kk * 64 + (tx << 2)];
            bd[0] = pk2(bv.x, bv.x); bd[1] = pk2(bv.y, bv.y);
            bd[2] = pk2(bv.z, bv.z); bd[3] = pk2(bv.w, bv.w);
#pragma unroll
            for (int p = 0; p < 4; p++)
#pragma unroll
                for (int j = 0; j < 4; j++)
                    fma2(op[p][j], ap[p], bd[j]);
        }
    }

    // rowsum reduce across the 16 tx lanes
#pragma unroll
    for (int i = 0; i < 8; i++) {
        float v = rs[i];
        v += __shfl_xor_sync(0xffffffffu, v, 1, 16);
        v += __shfl_xor_sync(0xffffffffu, v, 2, 16);
        v += __shfl_xor_sync(0xffffffffu, v, 4, 16);
        v += __shfl_xor_sync(0xffffffffu, v, 8, 16);
        rs[i] = v;
    }
    if (tx == 0) {
#pragma unroll
        for (int i = 0; i < 8; i++)
            g_rowsum[(size_t)bh * N_ + q0 + (ty << 3) + i] = rs[i];
    }

    // normalized attention output -> g_ao[b, row, h*64+hd]
    float o[8][4];
#pragma unroll
    for (int p = 0; p < 4; p++)
#pragma unroll
        for (int j = 0; j < 4; j++) {
            float2 v = up2(op[p][j]);
            o[2 * p][j] = v.x; o[2 * p + 1][j] = v.y;
        }
#pragma unroll
    for (int i = 0; i < 8; i++) {
        float inv = 1.0f / rs[i];
        int row = q0 + (ty << 3) + i;
        float* p = g_ao + ((size_t)b * N_ + row) * D_ + h * HD_ + (tx << 2);
        *(float4*)p = make_float4(o[i][0] * inv, o[i][1] * inv,
                                  o[i][2] * inv, o[i][3] * inv);
    }
}

// =============================================================================
// Kernel 3: normalize attn in place
// =============================================================================
__global__ void __launch_bounds__(256) norm_kernel(float* __restrict__ attn) {
    size_t i = (size_t)blockIdx.x * 256 + threadIdx.x;
    const size_t total = (size_t)BH_ * N_ * N_ / 4;
    if (i >= total) return;
    size_t e0 = i << 2;
    int row = (int)(e0 >> 11);
    float inv = 1.0f / g_rowsum[row];
    float4 v = ((float4*)attn)[i];
    v.x *= inv; v.y *= inv; v.z *= inv; v.w *= inv;
    ((float4*)attn)[i] = v;
}

// =============================================================================
// Kernel 4: output projection (f32x2 inner loop)
// =============================================================================
__global__ void __launch_bounds__(256) out_gemm(const float* __restrict__ W,
                                                const float* __restrict__ bias,
                                                float* __restrict__ out) {
    __shared__ float As2[8][264];
    __shared__ float Bs[8][132];
    int tid = threadIdx.x;
    int tx = tid & 15, ty = tid >> 4;
    int m0 = blockIdx.y << 7, n0 = blockIdx.x << 7;

    ull accp[8][4];
#pragma unroll
    for (int i = 0; i < 8; i++)
#pragma unroll
        for (int j = 0; j < 4; j++) accp[i][j] = 0ULL;

    int lr = tid >> 1;
    int lc = (tid & 1) << 2;
    const float* Ap = g_ao + (size_t)(m0 + lr) * 1024 + lc;
    const float* Wp = W + (size_t)(n0 + lr) * 1024 + lc;

    float4 av = *(const float4*)(Ap);
    float4 wv = *(const float4*)(Wp);

    for (int k0 = 0; k0 < 1024; k0 += 8) {
        __syncthreads();
        *(ull*)&As2[lc + 0][2 * lr] = pk2(av.x, av.x);
        *(ull*)&As2[lc + 1][2 * lr] = pk2(av.y, av.y);
        *(ull*)&As2[lc + 2][2 * lr] = pk2(av.z, av.z);
        *(ull*)&As2[lc + 3][2 * lr] = pk2(av.w, av.w);
        Bs[lc + 0][lr] = wv.x; Bs[lc + 1][lr] = wv.y;
        Bs[lc + 2][lr] = wv.z; Bs[lc + 3][lr] = wv.w;
        __syncthreads();
        if (k0 + 8 < 1024) {
            av = *(const float4*)(Ap + k0 + 8);
            wv = *(const float4*)(Wp + k0 + 8);
        }
#pragma unroll
        for (int kk = 0; kk < 8; kk++) {
            ull ap[8], bp[4];
#pragma unroll
            for (int u = 0; u < 4; u++) {
                ulonglong2 t = *(const ulonglong2*)&As2[kk][(ty << 4) + (u << 2)];
                ap[2 * u] = t.x; ap[2 * u + 1] = t.y;
            }
            {
                ulonglong2 t0 = *(const ulonglong2*)&Bs[kk][tx << 3];
                ulonglong2 t1 = *(const ulonglong2*)&Bs[kk][(tx << 3) + 4];
                bp[0] = t0.x; bp[1] = t0.y; bp[2] = t1.x; bp[3] = t1.y;
            }
#pragma unroll
            for (int i = 0; i < 8; i++)
#pragma unroll
                for (int j = 0; j < 4; j++)
                    fma2(accp[i][j], ap[i], bp[j]);
        }
    }

    int ncol = n0 + (tx << 3);
    float bv[8];
#pragma unroll
    for (int j = 0; j < 8; j++) bv[j] = bias[ncol + j];
#pragma unroll
    for (int i = 0; i < 8; i++) {
        int m = m0 + (ty << 3) + i;
        float* p = out + (size_t)m * 1024 + ncol;
        float2 c0 = up2(accp[i][0]), c1 = up2(accp[i][1]);
        float2 c2 = up2(accp[i][2]), c3 = up2(accp[i][3]);
        *(float4*)p = make_float4(c0.x + bv[0], c0.y + bv[1], c1.x + bv[2], c1.y + bv[3]);
        *(float4*)(p + 4) = make_float4(c2.x + bv[4], c2.y + bv[5], c3.x + bv[6], c3.y + bv[7]);
    }
}

// =============================================================================
extern "C" void kernel_launch(void* const* d_in, const int* in_sizes, int n_in,
                              void* d_out, int out_size) {
    const float* query = (const float*)d_in[0];
    const float* w_in  = (const float*)d_in[4];
    const float* b_in  = (const float*)d_in[5];
    const float* w_out = (const float*)d_in[6];
    const float* b_out = (const float*)d_in[7];
    const float* rpe   = (const float*)d_in[8];

    float* out  = (float*)d_out;
    const long long out_elems  = (long long)B_ * N_ * D_;
    const long long attn_elems = (long long)BH_ * N_ * N_;
    int write_attn = ((long long)out_size >= out_elems + attn_elems) ? 1 : 0;
    float* attn = out + out_elems;

    cudaFuncSetAttribute(attn_kernel, cudaFuncAttributeMaxDynamicSharedMemorySize,
                         ATTN_SMEM);

    qkv_gemm<<<dim3(24, 32), 256>>>(query, w_in, b_in);
    attn_kernel<<<dim3(16, 16, 2), 256, ATTN_SMEM>>>(attn, rpe, write_attn);
    if (write_attn) {
        const int total_f4 = (int)((long long)BH_ * N_ * N_ / 4);
        norm_kernel<<<(total_f4 + 255) / 256, 256>>>(attn);
    }
    out_gemm<<<dim3(8, 32), 256>>>(w_out, b_out, out);
}

// round 4
// speedup vs baseline: 1.3715x; 1.3715x over previous
#include <cuda_runtime.h>
#include <cuda_bf16.h>
#include <cstdint>

#define B_  2
#define N_  2048
#define D_  1024
#define H_  16
#define HD_ 64
#define S_  2048
#define BH_ (B_*H_)

// ---------------- scratch ----------------------------------------------------
static __device__ float g_q[(size_t)BH_*N_*HD_];     // [b,h,n,hd]
static __device__ float g_k[(size_t)BH_*N_*HD_];
static __device__ float g_v[(size_t)BH_*N_*HD_];
static __device__ float g_ao[(size_t)B_*N_*D_];      // attn_out [b,n,d]
static __device__ float g_rowsum[(size_t)BH_*N_];

// split-bf16 operands
static __device__ __nv_bfloat16 g_qh[(size_t)4096*1024];
static __device__ __nv_bfloat16 g_ql[(size_t)4096*1024];
static __device__ __nv_bfloat16 g_wih[(size_t)3072*1024];
static __device__ __nv_bfloat16 g_wil[(size_t)3072*1024];
static __device__ __nv_bfloat16 g_aoh[(size_t)4096*1024];
static __device__ __nv_bfloat16 g_aol[(size_t)4096*1024];
static __device__ __nv_bfloat16 g_woh[(size_t)1024*1024];
static __device__ __nv_bfloat16 g_wol[(size_t)1024*1024];

// ---------------- helpers ----------------------------------------------------
__device__ __forceinline__ uint32_t smem_u32(const void* p) {
    uint32_t a;
    asm("{ .reg .u64 t; cvta.to.shared.u64 t, %1; cvt.u32.u64 %0, t; }"
        : "=r"(a) : "l"(p));
    return a;
}
__device__ __forceinline__ void cp16(uint32_t dst, const void* src) {
    asm volatile("cp.async.cg.shared.global [%0], [%1], 16;" :: "r"(dst), "l"(src));
}
#define CP_COMMIT asm volatile("cp.async.commit_group;" ::: "memory")
#define CP_WAIT0  asm volatile("cp.async.wait_group 0;" ::: "memory")
#define CP_WAIT1  asm volatile("cp.async.wait_group 1;" ::: "memory")

__device__ __forceinline__ void ldsm4(uint32_t& r0, uint32_t& r1, uint32_t& r2,
                                      uint32_t& r3, uint32_t addr) {
    asm volatile("ldmatrix.sync.aligned.m8n8.x4.shared.b16 {%0,%1,%2,%3}, [%4];"
                 : "=r"(r0), "=r"(r1), "=r"(r2), "=r"(r3) : "r"(addr));
}
__device__ __forceinline__ void mma16816(float* c, const uint32_t* a,
                                         const uint32_t* b) {
    asm volatile(
        "mma.sync.aligned.m16n8k16.row.col.f32.bf16.bf16.f32 "
        "{%0,%1,%2,%3}, {%4,%5,%6,%7}, {%8,%9}, {%0,%1,%2,%3};"
        : "+f"(c[0]), "+f"(c[1]), "+f"(c[2]), "+f"(c[3])
        : "r"(a[0]), "r"(a[1]), "r"(a[2]), "r"(a[3]), "r"(b[0]), "r"(b[1]));
}

// =============================================================================
// fp32 -> bf16 hi/lo split
// =============================================================================
__global__ void __launch_bounds__(256) cvt_kernel(const float* __restrict__ x,
                                                  __nv_bfloat16* __restrict__ hi,
                                                  __nv_bfloat16* __restrict__ lo,
                                                  int n4) {
    int i = blockIdx.x * 256 + threadIdx.x;
    if (i >= n4) return;
    float4 v = ((const float4*)x)[i];
    __nv_bfloat16 h0 = __float2bfloat16(v.x), h1 = __float2bfloat16(v.y);
    __nv_bfloat16 h2 = __float2bfloat16(v.z), h3 = __float2bfloat16(v.w);
    __nv_bfloat16 l0 = __float2bfloat16(v.x - __bfloat162float(h0));
    __nv_bfloat16 l1 = __float2bfloat16(v.y - __bfloat162float(h1));
    __nv_bfloat16 l2 = __float2bfloat16(v.z - __bfloat162float(h2));
    __nv_bfloat16 l3 = __float2bfloat16(v.w - __bfloat162float(h3));
    ((__nv_bfloat162*)hi)[2 * i] = __nv_bfloat162(h0, h1);
    ((__nv_bfloat162*)hi)[2 * i + 1] = __nv_bfloat162(h2, h3);
    ((__nv_bfloat162*)lo)[2 * i] = __nv_bfloat162(l0, l1);
    ((__nv_bfloat162*)lo)[2 * i + 1] = __nv_bfloat162(l2, l3);
}

// =============================================================================
// Split-bf16 GEMM via mma.sync (HMMA): C[m,n] = sum_k A[m,k]*B[n,k] + bias[n]
// 128x128 tile, BK=32, cp.async double buffer, 8 warps (4m x 2n), warp 32x64.
// =============================================================================
#define BKD   32
#define SSTR  40                          // smem row stride (bf16) = 80B
#define ARRB  (128*SSTR*2)                // one operand array per stage (bytes)
#define STAGE (4*ARRB)
#define GEMM_SMEM (2*STAGE)               // 81920 B

template<bool QKV>
__global__ void __launch_bounds__(256) mma_gemm(
        const __nv_bfloat16* __restrict__ Ah_g, const __nv_bfloat16* __restrict__ Al_g,
        const __nv_bfloat16* __restrict__ Bh_g, const __nv_bfloat16* __restrict__ Bl_g,
        const float* __restrict__ bias, float* __restrict__ outp) {
    extern __shared__ char smem[];
    uint32_t sb = smem_u32(smem);
    int tid = threadIdx.x, lane = tid & 31, wid = tid >> 5;
    int m0 = blockIdx.y << 7, n0 = blockIdx.x << 7;
    int wm = wid >> 1, wn = wid & 1;

    const __nv_bfloat16* base[4] = {
        Ah_g + (size_t)m0 * 1024, Al_g + (size_t)m0 * 1024,
        Bh_g + (size_t)n0 * 1024, Bl_g + (size_t)n0 * 1024 };

    float c[2][8][4];
#pragma unroll
    for (int mt = 0; mt < 2; mt++)
#pragma unroll
        for (int nt = 0; nt < 8; nt++)
#pragma unroll
            for (int q = 0; q < 4; q++) c[mt][nt][q] = 0.f;

    int r_ld = tid >> 2, c_ld = (tid & 3) << 3;     // gmem->smem mapping

    // issue chunk 0
    {
        int k0 = 0;
#pragma unroll
        for (int arr = 0; arr < 4; arr++)
#pragma unroll
            for (int j = 0; j < 2; j++) {
                int r = r_ld + j * 64;
                cp16(sb + arr * ARRB + (uint32_t)(r * SSTR + c_ld) * 2,
                     base[arr] + (size_t)r * 1024 + k0 + c_ld);
            }
        CP_COMMIT;
    }

#pragma unroll 1
    for (int t = 0; t < 32; t++) {
        if (t + 1 < 32) {
            int s = (t + 1) & 1, k0 = (t + 1) << 5;
#pragma unroll
            for (int arr = 0; arr < 4; arr++)
#pragma unroll
                for (int j = 0; j < 2; j++) {
                    int r = r_ld + j * 64;
                    cp16(sb + (uint32_t)s * STAGE + arr * ARRB +
                             (uint32_t)(r * SSTR + c_ld) * 2,
                         base[arr] + (size_t)r * 1024 + k0 + c_ld);
                }
            CP_COMMIT;
            CP_WAIT1;
        } else {
            CP_WAIT0;
        }
        __syncthreads();

        uint32_t st = sb + (uint32_t)(t & 1) * STAGE;
#pragma unroll
        for (int kk = 0; kk < 2; kk++) {
            uint32_t bh[8][2], bl[8][2];
#pragma unroll
            for (int ng = 0; ng < 4; ng++) {
                int brow = wn * 64 + ng * 16 + (lane & 7) + ((lane & 16) >> 1);
                int bcol = kk * 16 + ((lane >> 3) & 1) * 8;
                uint32_t ba = st + 2 * ARRB + (uint32_t)(brow * SSTR + bcol) * 2;
                ldsm4(bh[2 * ng][0], bh[2 * ng][1], bh[2 * ng + 1][0],
                      bh[2 * ng + 1][1], ba);
                ldsm4(bl[2 * ng][0], bl[2 * ng][1], bl[2 * ng + 1][0],
                      bl[2 * ng + 1][1], ba + ARRB);
            }
#pragma unroll
            for (int mt = 0; mt < 2; mt++) {
                int arow = wm * 32 + mt * 16 + (lane & 15);
                int acol = kk * 16 + (lane >> 4) * 8;
                uint32_t aa = st + (uint32_t)(arow * SSTR + acol) * 2;
                uint32_t ah[4], al[4];
                ldsm4(ah[0], ah[1], ah[2], ah[3], aa);
                ldsm4(al[0], al[1], al[2], al[3], aa + ARRB);
#pragma unroll
                for (int nt = 0; nt < 8; nt++) {
                    mma16816(c[mt][nt], ah, bh[nt]);
                    mma16816(c[mt][nt], ah, bl[nt]);
                    mma16816(c[mt][nt], al, bh[nt]);
                }
            }
        }
        __syncthreads();
    }

    // ---------------- epilogue ----------------
#pragma unroll
    for (int mt = 0; mt < 2; mt++) {
        int m = m0 + wm * 32 + mt * 16 + (lane >> 2);
#pragma unroll
        for (int nt = 0; nt < 8; nt++) {
            int n = n0 + wn * 64 + nt * 8 + ((lane & 3) << 1);
            float b0 = bias[n], b1 = bias[n + 1];
            float2 v0 = make_float2(c[mt][nt][0] + b0, c[mt][nt][1] + b1);
            float2 v1 = make_float2(c[mt][nt][2] + b0, c[mt][nt][3] + b1);
            if (QKV) {
                int sect = n >> 10;
                int h = (n & 1023) >> 6, hd = n & 63;
                float* dst = (sect == 0) ? g_q : ((sect == 1) ? g_k : g_v);
                int bb = m >> 11, row = m & 2047;
                float* p = dst + (((size_t)(bb * H_ + h) * N_ + row) * HD_ + hd);
                *(float2*)p = v0;
                *(float2*)(p + 8 * HD_) = v1;      // row+8, same head
            } else {
                float* p = outp + (size_t)m * 1024 + n;
                *(float2*)p = v0;
                *(float2*)(p + 8 * 1024) = v1;
            }
        }
    }
}

// =============================================================================
// Fused attention (R1 scalar version — known good)
// =============================================================================
#define QS_OFF 0
#define KS_OFF (128*65)
#define VS_OFF (KS_OFF + 64*65)
#define ES_OFF (VS_OFF + 64*64)
#define RC_OFF (ES_OFF + 128*65)
#define ATTN_SMEM ((RC_OFF + 2048) * 4)

__global__ void __launch_bounds__(256, 2) attn_kernel(float* __restrict__ attn,
                                                      const float* __restrict__ rpe,
                                                      int write_attn) {
    extern __shared__ float sm[];
    float* qs = sm + QS_OFF;
    float* ks = sm + KS_OFF;
    float* vs = sm + VS_OFF;
    float* es = sm + ES_OFF;
    float* rc = sm + RC_OFF;

    int qt = blockIdx.x, h = blockIdx.y, b = blockIdx.z;
    int bh = b * H_ + h;
    int tid = threadIdx.x, tx = tid & 15, ty = tid >> 4;
    int q0 = qt << 7;

    for (int i = tid; i < S_; i += 256) rc[i] = rpe[(size_t)i * H_ + h];

    const float* qg = g_q + ((size_t)bh * N_ + q0) * HD_;
#pragma unroll
    for (int it = 0; it < 8; it++) {
        int f4 = tid + it * 256;
        int row = f4 >> 4, c = (f4 & 15) << 2;
        float4 v = *(const float4*)(qg + row * 64 + c);
        float* p = qs + row * 65 + c;
        p[0] = v.x; p[1] = v.y; p[2] = v.z; p[3] = v.w;
    }

    float o[8][4];
    float rs[8];
#pragma unroll
    for (int i = 0; i < 8; i++) {
        rs[i] = 0.f;
#pragma unroll
        for (int j = 0; j < 4; j++) o[i][j] = 0.f;
    }

    const float scale = 0.125f;

    for (int t = 0; t < N_ / 64; t++) {
        __syncthreads();
        const float* kg = g_k + ((size_t)bh * N_ + t * 64) * HD_;
        const float* vg = g_v + ((size_t)bh * N_ + t * 64) * HD_;
#pragma unroll
        for (int it = 0; it < 4; it++) {
            int f4 = tid + it * 256;
            int row = f4 >> 4, c = (f4 & 15) << 2;
            float4 kv = *(const float4*)(kg + row * 64 + c);
            float* kp = ks + row * 65 + c;
            kp[0] = kv.x; kp[1] = kv.y; kp[2] = kv.z; kp[3] = kv.w;
            *(float4*)(vs + row * 64 + c) = *(const float4*)(vg + row * 64 + c);
        }
        __syncthreads();

        float s[8][4];
#pragma unroll
        for (int i = 0; i < 8; i++)
#pragma unroll
            for (int j = 0; j < 4; j++) s[i][j] = 0.f;
#pragma unroll 8
        for (int hd = 0; hd < 64; hd++) {
            float a[8], bb[4];
#pragma unroll
            for (int i = 0; i < 8; i++) a[i] = qs[((ty << 3) + i) * 65 + hd];
#pragma unroll
            for (int j = 0; j < 4; j++) bb[j] = ks[((tx << 2) + j) * 65 + hd];
#pragma unroll
            for (int i = 0; i < 8; i++)
#pragma unroll
                for (int j = 0; j < 4; j++)
                    s[i][j] = fmaf(a[i], bb[j], s[i][j]);
        }

        int k0 = t * 64;
#pragma unroll
        for (int i = 0; i < 8; i++) {
            int qi = q0 + (ty << 3) + i;
            float e4[4];
#pragma unroll
            for (int j = 0; j < 4; j++) {
                int kj = k0 + (tx << 2) + j;
                int d = qi - kj; if (d < 0) d = -d;
                float e = __expf(fmaf(s[i][j], scale, rc[d]));
                e4[j] = e;
                rs[i] += e;
                es[((ty << 3) + i) * 65 + (tx << 2) + j] = e;
            }
            if (write_attn)
                *(float4*)&attn[((size_t)bh * N_ + qi) * N_ + k0 + (tx << 2)] =
                    make_float4(e4[0], e4[1], e4[2], e4[3]);
        }
        __syncthreads();

#pragma unroll 4
        for (int kk = 0; kk < 64; kk++) {
            float a[8];
#pragma unroll
            for (int i = 0; i < 8; i++) a[i] = es[((ty << 3) + i) * 65 + kk];
            float4 bv = *(const float4*)(vs + kk * 64 + (tx << 2));
            float bb[4] = {bv.x, bv.y, bv.z, bv.w};
#pragma unroll
            for (int i = 0; i < 8; i++)
#pragma unroll
                for (int j = 0; j < 4; j++)
                    o[i][j] = fmaf(a[i], bb[j], o[i][j]);
        }
    }

#pragma unroll
    for (int i = 0; i < 8; i++) {
        float v = rs[i];
        v += __shfl_xor_sync(0xffffffffu, v, 1, 16);
        v += __shfl_xor_sync(0xffffffffu, v, 2, 16);
        v += __shfl_xor_sync(0xffffffffu, v, 4, 16);
        v += __shfl_xor_sync(0xffffffffu, v, 8, 16);
        rs[i] = v;
    }
    if (tx == 0) {
#pragma unroll
        for (int i = 0; i < 8; i++)
            g_rowsum[(size_t)bh * N_ + q0 + (ty << 3) + i] = rs[i];
    }

#pragma unroll
    for (int i = 0; i < 8; i++) {
        float inv = 1.0f / rs[i];
        int row = q0 + (ty << 3) + i;
        float* p = g_ao + ((size_t)b * N_ + row) * D_ + h * HD_ + (tx << 2);
        *(float4*)p = make_float4(o[i][0] * inv, o[i][1] * inv,
                                  o[i][2] * inv, o[i][3] * inv);
    }
}

// =============================================================================
__global__ void __launch_bounds__(256) norm_kernel(float* __restrict__ attn) {
    size_t i = (size_t)blockIdx.x * 256 + threadIdx.x;
    const size_t total = (size_t)BH_ * N_ * N_ / 4;
    if (i >= total) return;
    size_t e0 = i << 2;
    int row = (int)(e0 >> 11);
    float inv = 1.0f / g_rowsum[row];
    float4 v = ((float4*)attn)[i];
    v.x *= inv; v.y *= inv; v.z *= inv; v.w *= inv;
    ((float4*)attn)[i] = v;
}

// =============================================================================
extern "C" void kernel_launch(void* const* d_in, const int* in_sizes, int n_in,
                              void* d_out, int out_size) {
    const float* query = (const float*)d_in[0];
    const float* w_in  = (const float*)d_in[4];
    const float* b_in  = (const float*)d_in[5];
    const float* w_out = (const float*)d_in[6];
    const float* b_out = (const float*)d_in[7];
    const float* rpe   = (const float*)d_in[8];

    float* out  = (float*)d_out;
    const long long out_elems  = (long long)B_ * N_ * D_;
    const long long attn_elems = (long long)BH_ * N_ * N_;
    int write_attn = ((long long)out_size >= out_elems + attn_elems) ? 1 : 0;
    float* attn = out + out_elems;

    cudaFuncSetAttribute(attn_kernel, cudaFuncAttributeMaxDynamicSharedMemorySize,
                         ATTN_SMEM);
    cudaFuncSetAttribute(mma_gemm<true>, cudaFuncAttributeMaxDynamicSharedMemorySize,
                         GEMM_SMEM);
    cudaFuncSetAttribute(mma_gemm<false>, cudaFuncAttributeMaxDynamicSharedMemorySize,
                         GEMM_SMEM);

    __nv_bfloat16 *qh, *ql, *wih, *wil, *aoh, *aol, *woh, *wol;
    float *ao;
    cudaGetSymbolAddress((void**)&qh,  g_qh);
    cudaGetSymbolAddress((void**)&ql,  g_ql);
    cudaGetSymbolAddress((void**)&wih, g_wih);
    cudaGetSymbolAddress((void**)&wil, g_wil);
    cudaGetSymbolAddress((void**)&aoh, g_aoh);
    cudaGetSymbolAddress((void**)&aol, g_aol);
    cudaGetSymbolAddress((void**)&woh, g_woh);
    cudaGetSymbolAddress((void**)&wol, g_wol);
    cudaGetSymbolAddress((void**)&ao,  g_ao);

    cvt_kernel<<<4096, 256>>>(query, qh, ql, 4096 * 1024 / 4);
    cvt_kernel<<<3072, 256>>>(w_in, wih, wil, 3072 * 1024 / 4);
    cvt_kernel<<<1024, 256>>>(w_out, woh, wol, 1024 * 1024 / 4);

    mma_gemm<true><<<dim3(24, 32), 256, GEMM_SMEM>>>(qh, ql, wih, wil, b_in, nullptr);

    attn_kernel<<<dim3(16, 16, 2), 256, ATTN_SMEM>>>(attn, rpe, write_attn);
    if (write_attn) {
        const int total_f4 = (int)((long long)BH_ * N_ * N_ / 4);
        norm_kernel<<<(total_f4 + 255) / 256, 256>>>(attn);
    }

    cvt_kernel<<<4096, 256>>>(ao, aoh, aol, 4096 * 1024 / 4);
    mma_gemm<false><<<dim3(8, 32), 256, GEMM_SMEM>>>(aoh, aol, woh, wol, b_out, out);
}

// round 5
// speedup vs baseline: 2.0646x; 1.5053x over previous
#include <cuda_runtime.h>
#include <cuda_bf16.h>
#include <cstdint>

#define B_  2
#define N_  2048
#define D_  1024
#define H_  16
#define HD_ 64
#define S_  2048
#define BH_ (B_*H_)

// ---------------- scratch ----------------------------------------------------
static __device__ float g_ao[(size_t)B_*N_*D_];      // attn_out [b,n,d]
static __device__ float g_rowsum[(size_t)BH_*N_];

// split-bf16 projection operands
static __device__ __nv_bfloat16 g_xh[(size_t)4096*1024];
static __device__ __nv_bfloat16 g_xl[(size_t)4096*1024];
static __device__ __nv_bfloat16 g_wih[(size_t)3072*1024];
static __device__ __nv_bfloat16 g_wil[(size_t)3072*1024];
static __device__ __nv_bfloat16 g_aoh[(size_t)4096*1024];
static __device__ __nv_bfloat16 g_aol[(size_t)4096*1024];
static __device__ __nv_bfloat16 g_woh[(size_t)1024*1024];
static __device__ __nv_bfloat16 g_wol[(size_t)1024*1024];

// split-bf16 attention operands (written by qkv epilogue)
static __device__ __nv_bfloat16 g_Qh[(size_t)BH_*N_*HD_];   // [bh,n,hd]
static __device__ __nv_bfloat16 g_Ql[(size_t)BH_*N_*HD_];
static __device__ __nv_bfloat16 g_Kh[(size_t)BH_*N_*HD_];
static __device__ __nv_bfloat16 g_Kl[(size_t)BH_*N_*HD_];
static __device__ __nv_bfloat16 g_Vth[(size_t)BH_*HD_*N_];  // [bh,hd,n] transposed
static __device__ __nv_bfloat16 g_Vtl[(size_t)BH_*HD_*N_];

// ---------------- helpers ----------------------------------------------------
__device__ __forceinline__ uint32_t smem_u32(const void* p) {
    uint32_t a;
    asm("{ .reg .u64 t; cvta.to.shared.u64 t, %1; cvt.u32.u64 %0, t; }"
        : "=r"(a) : "l"(p));
    return a;
}
__device__ __forceinline__ void cp16(uint32_t dst, const void* src) {
    asm volatile("cp.async.cg.shared.global [%0], [%1], 16;" :: "r"(dst), "l"(src));
}
#define CP_COMMIT asm volatile("cp.async.commit_group;" ::: "memory")
#define CP_WAIT0  asm volatile("cp.async.wait_group 0;" ::: "memory")
#define CP_WAIT1  asm volatile("cp.async.wait_group 1;" ::: "memory")

__device__ __forceinline__ void ldsm4(uint32_t& r0, uint32_t& r1, uint32_t& r2,
                                      uint32_t& r3, uint32_t addr) {
    asm volatile("ldmatrix.sync.aligned.m8n8.x4.shared.b16 {%0,%1,%2,%3}, [%4];"
                 : "=r"(r0), "=r"(r1), "=r"(r2), "=r"(r3) : "r"(addr));
}
__device__ __forceinline__ void mma16816(float* c, const uint32_t* a,
                                         const uint32_t* b) {
    asm volatile(
        "mma.sync.aligned.m16n8k16.row.col.f32.bf16.bf16.f32 "
        "{%0,%1,%2,%3}, {%4,%5,%6,%7}, {%8,%9}, {%0,%1,%2,%3};"
        : "+f"(c[0]), "+f"(c[1]), "+f"(c[2]), "+f"(c[3])
        : "r"(a[0]), "r"(a[1]), "r"(a[2]), "r"(a[3]), "r"(b[0]), "r"(b[1]));
}
__device__ __forceinline__ uint32_t pkbf(float lo, float hi) {
    uint32_t d;
    asm("cvt.rn.bf16x2.f32 %0, %1, %2;" : "=r"(d) : "f"(hi), "f"(lo));
    return d;
}

// =============================================================================
// fp32 -> bf16 hi/lo split (for projection inputs)
// =============================================================================
__global__ void __launch_bounds__(256) cvt_kernel(const float* __restrict__ x,
                                                  __nv_bfloat16* __restrict__ hi,
                                                  __nv_bfloat16* __restrict__ lo,
                                                  int n4) {
    int i = blockIdx.x * 256 + threadIdx.x;
    if (i >= n4) return;
    float4 v = ((const float4*)x)[i];
    __nv_bfloat16 h0 = __float2bfloat16(v.x), h1 = __float2bfloat16(v.y);
    __nv_bfloat16 h2 = __float2bfloat16(v.z), h3 = __float2bfloat16(v.w);
    __nv_bfloat16 l0 = __float2bfloat16(v.x - __bfloat162float(h0));
    __nv_bfloat16 l1 = __float2bfloat16(v.y - __bfloat162float(h1));
    __nv_bfloat16 l2 = __float2bfloat16(v.z - __bfloat162float(h2));
    __nv_bfloat16 l3 = __float2bfloat16(v.w - __bfloat162float(h3));
    ((__nv_bfloat162*)hi)[2 * i] = __nv_bfloat162(h0, h1);
    ((__nv_bfloat162*)hi)[2 * i + 1] = __nv_bfloat162(h2, h3);
    ((__nv_bfloat162*)lo)[2 * i] = __nv_bfloat162(l0, l1);
    ((__nv_bfloat162*)lo)[2 * i + 1] = __nv_bfloat162(l2, l3);
}

// =============================================================================
// Split-bf16 GEMM via mma.sync: C[m,n] = sum_k A[m,k]*B[n,k] + bias[n]
// QKV=true: epilogue splits/scatters into g_Qh/Ql, g_Kh/Kl, g_Vth/Vtl.
// =============================================================================
#define SSTR  40
#define ARRB  (128*SSTR*2)
#define STAGE (4*ARRB)
#define GEMM_SMEM (2*STAGE)

__device__ __forceinline__ void split_st2(__nv_bfloat16* dh, __nv_bfloat16* dl,
                                          size_t idx, float2 v) {
    __nv_bfloat16 h0 = __float2bfloat16(v.x), h1 = __float2bfloat16(v.y);
    *(__nv_bfloat162*)(dh + idx) = __nv_bfloat162(h0, h1);
    *(__nv_bfloat162*)(dl + idx) = __nv_bfloat162(
        __float2bfloat16(v.x - __bfloat162float(h0)),
        __float2bfloat16(v.y - __bfloat162float(h1)));
}
__device__ __forceinline__ void split_st1(__nv_bfloat16* dh, __nv_bfloat16* dl,
                                          size_t idx, float v) {
    __nv_bfloat16 h = __float2bfloat16(v);
    dh[idx] = h;
    dl[idx] = __float2bfloat16(v - __bfloat162float(h));
}

template<bool QKV>
__global__ void __launch_bounds__(256) mma_gemm(
        const __nv_bfloat16* __restrict__ Ah_g, const __nv_bfloat16* __restrict__ Al_g,
        const __nv_bfloat16* __restrict__ Bh_g, const __nv_bfloat16* __restrict__ Bl_g,
        const float* __restrict__ bias, float* __restrict__ outp) {
    extern __shared__ char smem[];
    uint32_t sb = smem_u32(smem);
    int tid = threadIdx.x, lane = tid & 31, wid = tid >> 5;
    int m0 = blockIdx.y << 7, n0 = blockIdx.x << 7;
    int wm = wid >> 1, wn = wid & 1;

    const __nv_bfloat16* base[4] = {
        Ah_g + (size_t)m0 * 1024, Al_g + (size_t)m0 * 1024,
        Bh_g + (size_t)n0 * 1024, Bl_g + (size_t)n0 * 1024 };

    float c[2][8][4];
#pragma unroll
    for (int mt = 0; mt < 2; mt++)
#pragma unroll
        for (int nt = 0; nt < 8; nt++)
#pragma unroll
            for (int q = 0; q < 4; q++) c[mt][nt][q] = 0.f;

    int r_ld = tid >> 2, c_ld = (tid & 3) << 3;

    {
#pragma unroll
        for (int arr = 0; arr < 4; arr++)
#pragma unroll
            for (int j = 0; j < 2; j++) {
                int r = r_ld + j * 64;
                cp16(sb + arr * ARRB + (uint32_t)(r * SSTR + c_ld) * 2,
                     base[arr] + (size_t)r * 1024 + c_ld);
            }
        CP_COMMIT;
    }

#pragma unroll 1
    for (int t = 0; t < 32; t++) {
        if (t + 1 < 32) {
            int s = (t + 1) & 1, k0 = (t + 1) << 5;
#pragma unroll
            for (int arr = 0; arr < 4; arr++)
#pragma unroll
                for (int j = 0; j < 2; j++) {
                    int r = r_ld + j * 64;
                    cp16(sb + (uint32_t)s * STAGE + arr * ARRB +
                             (uint32_t)(r * SSTR + c_ld) * 2,
                         base[arr] + (size_t)r * 1024 + k0 + c_ld);
                }
            CP_COMMIT;
            CP_WAIT1;
        } else {
            CP_WAIT0;
        }
        __syncthreads();

        uint32_t st = sb + (uint32_t)(t & 1) * STAGE;
#pragma unroll
        for (int kk = 0; kk < 2; kk++) {
            uint32_t bh[8][2], bl[8][2];
#pragma unroll
            for (int ng = 0; ng < 4; ng++) {
                int brow = wn * 64 + ng * 16 + (lane & 7) + ((lane & 16) >> 1);
                int bcol = kk * 16 + ((lane >> 3) & 1) * 8;
                uint32_t ba = st + 2 * ARRB + (uint32_t)(brow * SSTR + bcol) * 2;
                ldsm4(bh[2 * ng][0], bh[2 * ng][1], bh[2 * ng + 1][0],
                      bh[2 * ng + 1][1], ba);
                ldsm4(bl[2 * ng][0], bl[2 * ng][1], bl[2 * ng + 1][0],
                      bl[2 * ng + 1][1], ba + ARRB);
            }
#pragma unroll
            for (int mt = 0; mt < 2; mt++) {
                int arow = wm * 32 + mt * 16 + (lane & 15);
                int acol = kk * 16 + (lane >> 4) * 8;
                uint32_t aa = st + (uint32_t)(arow * SSTR + acol) * 2;
                uint32_t ah[4], al[4];
                ldsm4(ah[0], ah[1], ah[2], ah[3], aa);
                ldsm4(al[0], al[1], al[2], al[3], aa + ARRB);
#pragma unroll
                for (int nt = 0; nt < 8; nt++) {
                    mma16816(c[mt][nt], ah, bh[nt]);
                    mma16816(c[mt][nt], ah, bl[nt]);
                    mma16816(c[mt][nt], al, bh[nt]);
                }
            }
        }
        __syncthreads();
    }

    // ---------------- epilogue ----------------
#pragma unroll
    for (int mt = 0; mt < 2; mt++) {
        int m = m0 + wm * 32 + mt * 16 + (lane >> 2);
#pragma unroll
        for (int nt = 0; nt < 8; nt++) {
            int n = n0 + wn * 64 + nt * 8 + ((lane & 3) << 1);
            float b0 = bias[n], b1 = bias[n + 1];
            float2 v0 = make_float2(c[mt][nt][0] + b0, c[mt][nt][1] + b1);
            float2 v1 = make_float2(c[mt][nt][2] + b0, c[mt][nt][3] + b1);
            if (QKV) {
                int sect = n >> 10;
                int h = (n & 1023) >> 6, hd = n & 63;
                int bb = m >> 11, row = m & 2047;
                int bh_i = bb * H_ + h;
                if (sect < 2) {
                    __nv_bfloat16* dh = sect == 0 ? g_Qh : g_Kh;
                    __nv_bfloat16* dl = sect == 0 ? g_Ql : g_Kl;
                    size_t p = ((size_t)bh_i * N_ + row) * HD_ + hd;
                    split_st2(dh, dl, p, v0);
                    split_st2(dh, dl, p + 8 * HD_, v1);
                } else {
                    size_t pb = ((size_t)bh_i * HD_ + hd) * N_ + row;
                    split_st1(g_Vth, g_Vtl, pb, v0.x);
                    split_st1(g_Vth, g_Vtl, pb + N_, v0.y);
                    split_st1(g_Vth, g_Vtl, pb + 8, v1.x);
                    split_st1(g_Vth, g_Vtl, pb + N_ + 8, v1.y);
                }
            } else {
                float* p = outp + (size_t)m * 1024 + n;
                *(float2*)p = v0;
                *(float2*)(p + 8 * 1024) = v1;
            }
        }
    }
}

// =============================================================================
// HMMA split-bf16 fused attention.
// Block = (qtile 128 rows, head, batch); 256 threads = 8 warps x 16 query rows.
// Per 64-key tile: S = QK^T (3 split MMAs), exp+bias -> write unnorm e to attn,
// e->bf16 A-frags in registers, O += e.V (3 split MMAs, V pre-transposed).
// =============================================================================
#define AT_STR 72
// bf16-unit offsets in smem
#define AQH 0
#define AQL (128*AT_STR)
#define AKH (AQH + 2*128*AT_STR)
#define AKL (AKH + 64*AT_STR)
#define AVH (AKL + 64*AT_STR)
#define AVL (AVH + 64*AT_STR)
#define ABF_END (AVL + 64*AT_STR)
#define ATTN_SMEM (ABF_END*2 + 2048*4)

__global__ void __launch_bounds__(256, 1) attn_kernel(float* __restrict__ attn,
                                                      const float* __restrict__ rpe,
                                                      int write_attn) {
    extern __shared__ char smc[];
    uint32_t sb = smem_u32(smc);
    float* rc = (float*)(smc + ABF_END * 2);

    int qt = blockIdx.x, h = blockIdx.y, b = blockIdx.z;
    int bh_i = b * H_ + h;
    int tid = threadIdx.x, lane = tid & 31, wm = tid >> 5;
    int q0 = qt << 7;

    for (int i = tid; i < S_; i += 256) rc[i] = rpe[(size_t)i * H_ + h];

    // ---- load Q (hi/lo) once ----
    const __nv_bfloat16* qhg = g_Qh + ((size_t)bh_i * N_ + q0) * HD_;
    const __nv_bfloat16* qlg = g_Ql + ((size_t)bh_i * N_ + q0) * HD_;
#pragma unroll
    for (int j = 0; j < 4; j++) {
        int u = tid + j * 256;                 // 0..1023
        int r = u >> 3, ch = (u & 7) << 3;
        cp16(sb + (uint32_t)(AQH + r * AT_STR + ch) * 2, qhg + (size_t)r * HD_ + ch);
        cp16(sb + (uint32_t)(AQL + r * AT_STR + ch) * 2, qlg + (size_t)r * HD_ + ch);
    }
    CP_COMMIT;

    float co[8][4];
#pragma unroll
    for (int nh = 0; nh < 8; nh++)
#pragma unroll
        for (int q = 0; q < 4; q++) co[nh][q] = 0.f;
    float rs0 = 0.f, rs1 = 0.f;

    const __nv_bfloat16* khg = g_Kh + (size_t)bh_i * N_ * HD_;
    const __nv_bfloat16* klg = g_Kl + (size_t)bh_i * N_ * HD_;
    const __nv_bfloat16* vhg = g_Vth + (size_t)bh_i * HD_ * N_;
    const __nv_bfloat16* vlg = g_Vtl + (size_t)bh_i * HD_ * N_;

    int row_q = q0 + wm * 16 + (lane >> 2);
    const float scale = 0.125f;

#pragma unroll 1
    for (int t = 0; t < N_ / 64; t++) {
        int k0g = t * 64;
        __syncthreads();     // previous tile's ldmatrix reads done
#pragma unroll
        for (int j = 0; j < 2; j++) {
            int u = tid + j * 256;             // 0..511
            int r = u >> 3, ch = (u & 7) << 3;
            cp16(sb + (uint32_t)(AKH + r * AT_STR + ch) * 2,
                 khg + (size_t)(k0g + r) * HD_ + ch);
            cp16(sb + (uint32_t)(AKL + r * AT_STR + ch) * 2,
                 klg + (size_t)(k0g + r) * HD_ + ch);
            cp16(sb + (uint32_t)(AVH + r * AT_STR + ch) * 2,
                 vhg + (size_t)r * N_ + k0g + ch);
            cp16(sb + (uint32_t)(AVL + r * AT_STR + ch) * 2,
                 vlg + (size_t)r * N_ + k0g + ch);
        }
        CP_COMMIT;
        CP_WAIT0;
        __syncthreads();

        // ---- S = Q.K^T ----
        float s[8][4];
#pragma unroll
        for (int nt = 0; nt < 8; nt++)
#pragma unroll
            for (int q = 0; q < 4; q++) s[nt][q] = 0.f;
#pragma unroll
        for (int ks = 0; ks < 4; ks++) {
            int arow = wm * 16 + (lane & 15);
            int acol = ks * 16 + (lane >> 4) * 8;
            uint32_t aa = sb + (uint32_t)(AQH + arow * AT_STR + acol) * 2;
            uint32_t ah[4], al[4];
            ldsm4(ah[0], ah[1], ah[2], ah[3], aa);
            ldsm4(al[0], al[1], al[2], al[3], aa + (AQL - AQH) * 2);
            uint32_t bh[8][2], bl[8][2];
#pragma unroll
            for (int ng = 0; ng < 4; ng++) {
                int brow = ng * 16 + (lane & 7) + ((lane & 16) >> 1);
                int bcol = ks * 16 + ((lane >> 3) & 1) * 8;
                uint32_t ba = sb + (uint32_t)(AKH + brow * AT_STR + bcol) * 2;
                ldsm4(bh[2 * ng][0], bh[2 * ng][1], bh[2 * ng + 1][0],
                      bh[2 * ng + 1][1], ba);
                ldsm4(bl[2 * ng][0], bl[2 * ng][1], bl[2 * ng + 1][0],
                      bl[2 * ng + 1][1], ba + (AKL - AKH) * 2);
            }
#pragma unroll
            for (int nt = 0; nt < 8; nt++) {
                mma16816(s[nt], ah, bh[nt]);
                mma16816(s[nt], ah, bl[nt]);
                mma16816(s[nt], al, bh[nt]);
            }
        }

        // ---- bias + exp + rowsum + attn store ----
#pragma unroll
        for (int nt = 0; nt < 8; nt++) {
            int col = k0g + nt * 8 + ((lane & 3) << 1);
            int d0 = row_q - col;     if (d0 < 0) d0 = -d0;
            int d1 = row_q - col - 1; if (d1 < 0) d1 = -d1;
            int d2 = row_q + 8 - col;     if (d2 < 0) d2 = -d2;
            int d3 = row_q + 8 - col - 1; if (d3 < 0) d3 = -d3;
            float e0 = __expf(fmaf(s[nt][0], scale, rc[d0]));
            float e1 = __expf(fmaf(s[nt][1], scale, rc[d1]));
            float e2 = __expf(fmaf(s[nt][2], scale, rc[d2]));
            float e3 = __expf(fmaf(s[nt][3], scale, rc[d3]));
            s[nt][0] = e0; s[nt][1] = e1; s[nt][2] = e2; s[nt][3] = e3;
            rs0 += e0 + e1;
            rs1 += e2 + e3;
            if (write_attn) {
                float* ap = attn + ((size_t)bh_i * N_ + row_q) * N_ + col;
                *(float2*)ap = make_float2(e0, e1);
                *(float2*)(ap + 8 * N_) = make_float2(e2, e3);
            }
        }

        // ---- O += e.V ----
#pragma unroll
        for (int ks = 0; ks < 4; ks++) {
            // e A-frags from registers (hi + lo split)
            uint32_t eah[4], eal[4];
            {
                float c0 = s[2 * ks][0], c1 = s[2 * ks][1];
                float c2 = s[2 * ks][2], c3 = s[2 * ks][3];
                float c4 = s[2 * ks + 1][0], c5 = s[2 * ks + 1][1];
                float c6 = s[2 * ks + 1][2], c7 = s[2 * ks + 1][3];
                eah[0] = pkbf(c0, c1); eah[1] = pkbf(c2, c3);
                eah[2] = pkbf(c4, c5); eah[3] = pkbf(c6, c7);
                float h;
                h = __bfloat162float(__float2bfloat16(c0)); c0 -= h;
                h = __bfloat162float(__float2bfloat16(c1)); c1 -= h;
                h = __bfloat162float(__float2bfloat16(c2)); c2 -= h;
                h = __bfloat162float(__float2bfloat16(c3)); c3 -= h;
                h = __bfloat162float(__float2bfloat16(c4)); c4 -= h;
                h = __bfloat162float(__float2bfloat16(c5)); c5 -= h;
                h = __bfloat162float(__float2bfloat16(c6)); c6 -= h;
                h = __bfloat162float(__float2bfloat16(c7)); c7 -= h;
                eal[0] = pkbf(c0, c1); eal[1] = pkbf(c2, c3);
                eal[2] = pkbf(c4, c5); eal[3] = pkbf(c6, c7);
            }
            uint32_t vbh[8][2], vbl[8][2];
#pragma unroll
            for (int ng = 0; ng < 4; ng++) {
                int brow = ng * 16 + (lane & 7) + ((lane & 16) >> 1);   // hd
                int bcol = ks * 16 + ((lane >> 3) & 1) * 8;             // key
                uint32_t ba = sb + (uint32_t)(AVH + brow * AT_STR + bcol) * 2;
                ldsm4(vbh[2 * ng][0], vbh[2 * ng][1], vbh[2 * ng + 1][0],
                      vbh[2 * ng + 1][1], ba);
                ldsm4(vbl[2 * ng][0], vbl[2 * ng][1], vbl[2 * ng + 1][0],
                      vbl[2 * ng + 1][1], ba + (AVL - AVH) * 2);
            }
#pragma unroll
            for (int nh = 0; nh < 8; nh++) {
                mma16816(co[nh], eah, vbh[nh]);
                mma16816(co[nh], eah, vbl[nh]);
                mma16816(co[nh], eal, vbh[nh]);
            }
        }
    }

    // ---- rowsum reduce over quad lanes ----
    rs0 += __shfl_xor_sync(0xffffffffu, rs0, 1);
    rs0 += __shfl_xor_sync(0xffffffffu, rs0, 2);
    rs1 += __shfl_xor_sync(0xffffffffu, rs1, 1);
    rs1 += __shfl_xor_sync(0xffffffffu, rs1, 2);
    if ((lane & 3) == 0) {
        g_rowsum[(size_t)bh_i * N_ + row_q] = rs0;
        g_rowsum[(size_t)bh_i * N_ + row_q + 8] = rs1;
    }

    // ---- normalized output -> g_ao[b, row, h*64+hd] ----
    float inv0 = 1.0f / rs0, inv1 = 1.0f / rs1;
#pragma unroll
    for (int nh = 0; nh < 8; nh++) {
        int hd = nh * 8 + ((lane & 3) << 1);
        float* p = g_ao + ((size_t)b * N_ + row_q) * D_ + h * HD_ + hd;
        *(float2*)p = make_float2(co[nh][0] * inv0, co[nh][1] * inv0);
        *(float2*)(p + 8 * D_) = make_float2(co[nh][2] * inv1, co[nh][3] * inv1);
    }
}

// =============================================================================
__global__ void __launch_bounds__(256) norm_kernel(float* __restrict__ attn) {
    size_t i = (size_t)blockIdx.x * 256 + threadIdx.x;
    const size_t total = (size_t)BH_ * N_ * N_ / 4;
    if (i >= total) return;
    size_t e0 = i << 2;
    int row = (int)(e0 >> 11);
    float inv = 1.0f / g_rowsum[row];
    float4 v = ((float4*)attn)[i];
    v.x *= inv; v.y *= inv; v.z *= inv; v.w *= inv;
    ((float4*)attn)[i] = v;
}

// =============================================================================
extern "C" void kernel_launch(void* const* d_in, const int* in_sizes, int n_in,
                              void* d_out, int out_size) {
    const float* query = (const float*)d_in[0];
    const float* w_in  = (const float*)d_in[4];
    const float* b_in  = (const float*)d_in[5];
    const float* w_out = (const float*)d_in[6];
    const float* b_out = (const float*)d_in[7];
    const float* rpe   = (const float*)d_in[8];

    float* out  = (float*)d_out;
    const long long out_elems  = (long long)B_ * N_ * D_;
    const long long attn_elems = (long long)BH_ * N_ * N_;
    int write_attn = ((long long)out_size >= out_elems + attn_elems) ? 1 : 0;
    float* attn = out + out_elems;

    cudaFuncSetAttribute(attn_kernel, cudaFuncAttributeMaxDynamicSharedMemorySize,
                         ATTN_SMEM);
    cudaFuncSetAttribute(mma_gemm<true>, cudaFuncAttributeMaxDynamicSharedMemorySize,
                         GEMM_SMEM);
    cudaFuncSetAttribute(mma_gemm<false>, cudaFuncAttributeMaxDynamicSharedMemorySize,
                         GEMM_SMEM);

    __nv_bfloat16 *xh, *xl, *wih, *wil, *aoh, *aol, *woh, *wol;
    float *ao;
    cudaGetSymbolAddress((void**)&xh,  g_xh);
    cudaGetSymbolAddress((void**)&xl,  g_xl);
    cudaGetSymbolAddress((void**)&wih, g_wih);
    cudaGetSymbolAddress((void**)&wil, g_wil);
    cudaGetSymbolAddress((void**)&aoh, g_aoh);
    cudaGetSymbolAddress((void**)&aol, g_aol);
    cudaGetSymbolAddress((void**)&woh, g_woh);
    cudaGetSymbolAddress((void**)&wol, g_wol);
    cudaGetSymbolAddress((void**)&ao,  g_ao);

    cvt_kernel<<<4096, 256>>>(query, xh, xl, 4096 * 1024 / 4);
    cvt_kernel<<<3072, 256>>>(w_in, wih, wil, 3072 * 1024 / 4);
    cvt_kernel<<<1024, 256>>>(w_out, woh, wol, 1024 * 1024 / 4);

    mma_gemm<true><<<dim3(24, 32), 256, GEMM_SMEM>>>(xh, xl, wih, wil, b_in, nullptr);

    attn_kernel<<<dim3(16, 16, 2), 256, ATTN_SMEM>>>(attn, rpe, write_attn);
    if (write_attn) {
        const int total_f4 = (int)((long long)BH_ * N_ * N_ / 4);
        norm_kernel<<<(total_f4 + 255) / 256, 256>>>(attn);
    }

    cvt_kernel<<<4096, 256>>>(ao, aoh, aol, 4096 * 1024 / 4);
    mma_gemm<false><<<dim3(8, 32), 256, GEMM_SMEM>>>(aoh, aol, woh, wol, b_out, out);
}

// round 6
// speedup vs baseline: 2.3940x; 1.1596x over previous
#include <cuda_runtime.h>
#include <cuda_bf16.h>
#include <cstdint>

#define B_  2
#define N_  2048
#define D_  1024
#define H_  16
#define HD_ 64
#define S_  2048
#define BH_ (B_*H_)

// ---------------- scratch ----------------------------------------------------
static __device__ float g_rowsum[(size_t)BH_*N_];

// split-bf16 projection operands
static __device__ __nv_bfloat16 g_xh[(size_t)4096*1024];
static __device__ __nv_bfloat16 g_xl[(size_t)4096*1024];
static __device__ __nv_bfloat16 g_wih[(size_t)3072*1024];
static __device__ __nv_bfloat16 g_wil[(size_t)3072*1024];
static __device__ __nv_bfloat16 g_aoh[(size_t)4096*1024];
static __device__ __nv_bfloat16 g_aol[(size_t)4096*1024];
static __device__ __nv_bfloat16 g_woh[(size_t)1024*1024];
static __device__ __nv_bfloat16 g_wol[(size_t)1024*1024];

// split-bf16 attention operands (written by qkv epilogue)
static __device__ __nv_bfloat16 g_Qh[(size_t)BH_*N_*HD_];   // [bh,n,hd]
static __device__ __nv_bfloat16 g_Ql[(size_t)BH_*N_*HD_];
static __device__ __nv_bfloat16 g_Kh[(size_t)BH_*N_*HD_];
static __device__ __nv_bfloat16 g_Kl[(size_t)BH_*N_*HD_];
static __device__ __nv_bfloat16 g_Vth[(size_t)BH_*HD_*N_];  // [bh,hd,n] transposed
static __device__ __nv_bfloat16 g_Vtl[(size_t)BH_*HD_*N_];

// ---------------- helpers ----------------------------------------------------
__device__ __forceinline__ uint32_t smem_u32(const void* p) {
    uint32_t a;
    asm("{ .reg .u64 t; cvta.to.shared.u64 t, %1; cvt.u32.u64 %0, t; }"
        : "=r"(a) : "l"(p));
    return a;
}
__device__ __forceinline__ void cp16(uint32_t dst, const void* src) {
    asm volatile("cp.async.cg.shared.global [%0], [%1], 16;" :: "r"(dst), "l"(src));
}
#define CP_COMMIT asm volatile("cp.async.commit_group;" ::: "memory")
#define CP_WAIT0  asm volatile("cp.async.wait_group 0;" ::: "memory")
#define CP_WAIT1  asm volatile("cp.async.wait_group 1;" ::: "memory")

__device__ __forceinline__ void ldsm4(uint32_t& r0, uint32_t& r1, uint32_t& r2,
                                      uint32_t& r3, uint32_t addr) {
    asm volatile("ldmatrix.sync.aligned.m8n8.x4.shared.b16 {%0,%1,%2,%3}, [%4];"
                 : "=r"(r0), "=r"(r1), "=r"(r2), "=r"(r3) : "r"(addr));
}
__device__ __forceinline__ void mma16816(float* c, const uint32_t* a,
                                         const uint32_t* b) {
    asm volatile(
        "mma.sync.aligned.m16n8k16.row.col.f32.bf16.bf16.f32 "
        "{%0,%1,%2,%3}, {%4,%5,%6,%7}, {%8,%9}, {%0,%1,%2,%3};"
        : "+f"(c[0]), "+f"(c[1]), "+f"(c[2]), "+f"(c[3])
        : "r"(a[0]), "r"(a[1]), "r"(a[2]), "r"(a[3]), "r"(b[0]), "r"(b[1]));
}
__device__ __forceinline__ uint32_t pkbf(float lo, float hi) {
    uint32_t d;
    asm("cvt.rn.bf16x2.f32 %0, %1, %2;" : "=r"(d) : "f"(hi), "f"(lo));
    return d;
}

// =============================================================================
// fp32 -> bf16 hi/lo split (for projection inputs)
// =============================================================================
__global__ void __launch_bounds__(256) cvt_kernel(const float* __restrict__ x,
                                                  __nv_bfloat16* __restrict__ hi,
                                                  __nv_bfloat16* __restrict__ lo,
                                                  int n4) {
    int i = blockIdx.x * 256 + threadIdx.x;
    if (i >= n4) return;
    float4 v = ((const float4*)x)[i];
    __nv_bfloat16 h0 = __float2bfloat16(v.x), h1 = __float2bfloat16(v.y);
    __nv_bfloat16 h2 = __float2bfloat16(v.z), h3 = __float2bfloat16(v.w);
    __nv_bfloat16 l0 = __float2bfloat16(v.x - __bfloat162float(h0));
    __nv_bfloat16 l1 = __float2bfloat16(v.y - __bfloat162float(h1));
    __nv_bfloat16 l2 = __float2bfloat16(v.z - __bfloat162float(h2));
    __nv_bfloat16 l3 = __float2bfloat16(v.w - __bfloat162float(h3));
    ((__nv_bfloat162*)hi)[2 * i] = __nv_bfloat162(h0, h1);
    ((__nv_bfloat162*)hi)[2 * i + 1] = __nv_bfloat162(h2, h3);
    ((__nv_bfloat162*)lo)[2 * i] = __nv_bfloat162(l0, l1);
    ((__nv_bfloat162*)lo)[2 * i + 1] = __nv_bfloat162(l2, l3);
}

// =============================================================================
// Split-bf16 GEMM via mma.sync (unchanged from R5 — proven)
// =============================================================================
#define SSTR  40
#define ARRB  (128*SSTR*2)
#define STAGE (4*ARRB)
#define GEMM_SMEM (2*STAGE)

__device__ __forceinline__ void split_st2(__nv_bfloat16* dh, __nv_bfloat16* dl,
                                          size_t idx, float2 v) {
    __nv_bfloat16 h0 = __float2bfloat16(v.x), h1 = __float2bfloat16(v.y);
    *(__nv_bfloat162*)(dh + idx) = __nv_bfloat162(h0, h1);
    *(__nv_bfloat162*)(dl + idx) = __nv_bfloat162(
        __float2bfloat16(v.x - __bfloat162float(h0)),
        __float2bfloat16(v.y - __bfloat162float(h1)));
}
__device__ __forceinline__ void split_st1(__nv_bfloat16* dh, __nv_bfloat16* dl,
                                          size_t idx, float v) {
    __nv_bfloat16 h = __float2bfloat16(v);
    dh[idx] = h;
    dl[idx] = __float2bfloat16(v - __bfloat162float(h));
}

template<bool QKV>
__global__ void __launch_bounds__(256) mma_gemm(
        const __nv_bfloat16* __restrict__ Ah_g, const __nv_bfloat16* __restrict__ Al_g,
        const __nv_bfloat16* __restrict__ Bh_g, const __nv_bfloat16* __restrict__ Bl_g,
        const float* __restrict__ bias, float* __restrict__ outp) {
    extern __shared__ char smem[];
    uint32_t sb = smem_u32(smem);
    int tid = threadIdx.x, lane = tid & 31, wid = tid >> 5;
    int m0 = blockIdx.y << 7, n0 = blockIdx.x << 7;
    int wm = wid >> 1, wn = wid & 1;

    const __nv_bfloat16* base[4] = {
        Ah_g + (size_t)m0 * 1024, Al_g + (size_t)m0 * 1024,
        Bh_g + (size_t)n0 * 1024, Bl_g + (size_t)n0 * 1024 };

    float c[2][8][4];
#pragma unroll
    for (int mt = 0; mt < 2; mt++)
#pragma unroll
        for (int nt = 0; nt < 8; nt++)
#pragma unroll
            for (int q = 0; q < 4; q++) c[mt][nt][q] = 0.f;

    int r_ld = tid >> 2, c_ld = (tid & 3) << 3;

    {
#pragma unroll
        for (int arr = 0; arr < 4; arr++)
#pragma unroll
            for (int j = 0; j < 2; j++) {
                int r = r_ld + j * 64;
                cp16(sb + arr * ARRB + (uint32_t)(r * SSTR + c_ld) * 2,
                     base[arr] + (size_t)r * 1024 + c_ld);
            }
        CP_COMMIT;
    }

#pragma unroll 1
    for (int t = 0; t < 32; t++) {
        if (t + 1 < 32) {
            int s = (t + 1) & 1, k0 = (t + 1) << 5;
#pragma unroll
            for (int arr = 0; arr < 4; arr++)
#pragma unroll
                for (int j = 0; j < 2; j++) {
                    int r = r_ld + j * 64;
                    cp16(sb + (uint32_t)s * STAGE + arr * ARRB +
                             (uint32_t)(r * SSTR + c_ld) * 2,
                         base[arr] + (size_t)r * 1024 + k0 + c_ld);
                }
            CP_COMMIT;
            CP_WAIT1;
        } else {
            CP_WAIT0;
        }
        __syncthreads();

        uint32_t st = sb + (uint32_t)(t & 1) * STAGE;
#pragma unroll
        for (int kk = 0; kk < 2; kk++) {
            uint32_t bh[8][2], bl[8][2];
#pragma unroll
            for (int ng = 0; ng < 4; ng++) {
                int brow = wn * 64 + ng * 16 + (lane & 7) + ((lane & 16) >> 1);
                int bcol = kk * 16 + ((lane >> 3) & 1) * 8;
                uint32_t ba = st + 2 * ARRB + (uint32_t)(brow * SSTR + bcol) * 2;
                ldsm4(bh[2 * ng][0], bh[2 * ng][1], bh[2 * ng + 1][0],
                      bh[2 * ng + 1][1], ba);
                ldsm4(bl[2 * ng][0], bl[2 * ng][1], bl[2 * ng + 1][0],
                      bl[2 * ng + 1][1], ba + ARRB);
            }
#pragma unroll
            for (int mt = 0; mt < 2; mt++) {
                int arow = wm * 32 + mt * 16 + (lane & 15);
                int acol = kk * 16 + (lane >> 4) * 8;
                uint32_t aa = st + (uint32_t)(arow * SSTR + acol) * 2;
                uint32_t ah[4], al[4];
                ldsm4(ah[0], ah[1], ah[2], ah[3], aa);
                ldsm4(al[0], al[1], al[2], al[3], aa + ARRB);
#pragma unroll
                for (int nt = 0; nt < 8; nt++) {
                    mma16816(c[mt][nt], ah, bh[nt]);
                    mma16816(c[mt][nt], ah, bl[nt]);
                    mma16816(c[mt][nt], al, bh[nt]);
                }
            }
        }
        __syncthreads();
    }

    // ---------------- epilogue ----------------
#pragma unroll
    for (int mt = 0; mt < 2; mt++) {
        int m = m0 + wm * 32 + mt * 16 + (lane >> 2);
#pragma unroll
        for (int nt = 0; nt < 8; nt++) {
            int n = n0 + wn * 64 + nt * 8 + ((lane & 3) << 1);
            float b0 = bias[n], b1 = bias[n + 1];
            float2 v0 = make_float2(c[mt][nt][0] + b0, c[mt][nt][1] + b1);
            float2 v1 = make_float2(c[mt][nt][2] + b0, c[mt][nt][3] + b1);
            if (QKV) {
                int sect = n >> 10;
                int h = (n & 1023) >> 6, hd = n & 63;
                int bb = m >> 11, row = m & 2047;
                int bh_i = bb * H_ + h;
                if (sect < 2) {
                    __nv_bfloat16* dh = sect == 0 ? g_Qh : g_Kh;
                    __nv_bfloat16* dl = sect == 0 ? g_Ql : g_Kl;
                    size_t p = ((size_t)bh_i * N_ + row) * HD_ + hd;
                    split_st2(dh, dl, p, v0);
                    split_st2(dh, dl, p + 8 * HD_, v1);
                } else {
                    size_t pb = ((size_t)bh_i * HD_ + hd) * N_ + row;
                    split_st1(g_Vth, g_Vtl, pb, v0.x);
                    split_st1(g_Vth, g_Vtl, pb + N_, v0.y);
                    split_st1(g_Vth, g_Vtl, pb + 8, v1.x);
                    split_st1(g_Vth, g_Vtl, pb + N_ + 8, v1.y);
                }
            } else {
                float* p = outp + (size_t)m * 1024 + n;
                *(float2*)p = v0;
                *(float2*)(p + 8 * 1024) = v1;
            }
        }
    }
}

// =============================================================================
// HMMA split-bf16 fused attention, 3-stage cp.async K/V pipeline.
// Epilogue writes normalized output as split-bf16 (aoh/aol) directly.
// =============================================================================
#define AT_STR 72
#define AQH 0
#define AQL (128*AT_STR)
#define AKV (2*128*AT_STR)                  // 18432 bf16 units
#define KVSTG (4*64*AT_STR)                 // 18432 bf16 units per stage
#define ABF_END (AKV + 3*KVSTG)
#define ATTN_SMEM (ABF_END*2 + 2048*4)      // 155648 B

__global__ void __launch_bounds__(256, 1) attn_kernel(float* __restrict__ attn,
                                                      const float* __restrict__ rpe,
                                                      int write_attn) {
    extern __shared__ char smc[];
    uint32_t sb = smem_u32(smc);
    float* rc = (float*)(smc + ABF_END * 2);

    int qt = blockIdx.x, h = blockIdx.y, b = blockIdx.z;
    int bh_i = b * H_ + h;
    int tid = threadIdx.x, lane = tid & 31, wm = tid >> 5;
    int q0 = qt << 7;

    for (int i = tid; i < S_; i += 256) rc[i] = rpe[(size_t)i * H_ + h];

    const __nv_bfloat16* qhg = g_Qh + ((size_t)bh_i * N_ + q0) * HD_;
    const __nv_bfloat16* qlg = g_Ql + ((size_t)bh_i * N_ + q0) * HD_;
    const __nv_bfloat16* khg = g_Kh + (size_t)bh_i * N_ * HD_;
    const __nv_bfloat16* klg = g_Kl + (size_t)bh_i * N_ * HD_;
    const __nv_bfloat16* vhg = g_Vth + (size_t)bh_i * HD_ * N_;
    const __nv_bfloat16* vlg = g_Vtl + (size_t)bh_i * HD_ * N_;

    // ---- Q load (own commit group) ----
#pragma unroll
    for (int j = 0; j < 4; j++) {
        int u = tid + j * 256;
        int r = u >> 3, ch = (u & 7) << 3;
        cp16(sb + (uint32_t)(AQH + r * AT_STR + ch) * 2, qhg + (size_t)r * HD_ + ch);
        cp16(sb + (uint32_t)(AQL + r * AT_STR + ch) * 2, qlg + (size_t)r * HD_ + ch);
    }
    CP_COMMIT;

    int r_ld = tid >> 3, c_ld = (tid & 7) << 3;
    auto issue_kv = [&](int t) {
        int k0g = t * 64;
        uint32_t stg = sb + (uint32_t)(AKV + (t % 3) * KVSTG) * 2;
#pragma unroll
        for (int j = 0; j < 2; j++) {
            int r = r_ld + j * 32, ch = c_ld;
            cp16(stg + (uint32_t)(0 * 4608 + r * AT_STR + ch) * 2,
                 khg + (size_t)(k0g + r) * HD_ + ch);
            cp16(stg + (uint32_t)(1 * 4608 + r * AT_STR + ch) * 2,
                 klg + (size_t)(k0g + r) * HD_ + ch);
            cp16(stg + (uint32_t)(2 * 4608 + r * AT_STR + ch) * 2,
                 vhg + (size_t)r * N_ + k0g + ch);
            cp16(stg + (uint32_t)(3 * 4608 + r * AT_STR + ch) * 2,
                 vlg + (size_t)r * N_ + k0g + ch);
        }
        CP_COMMIT;
    };
    issue_kv(0);
    issue_kv(1);

    float co[8][4];
#pragma unroll
    for (int nh = 0; nh < 8; nh++)
#pragma unroll
        for (int q = 0; q < 4; q++) co[nh][q] = 0.f;
    float rs0 = 0.f, rs1 = 0.f;

    int row_q = q0 + wm * 16 + (lane >> 2);
    const float scale = 0.125f;

#pragma unroll 1
    for (int t = 0; t < N_ / 64; t++) {
        if (t < 31) { CP_WAIT1; } else { CP_WAIT0; }
        __syncthreads();

        int k0g = t * 64;
        uint32_t kb = sb + (uint32_t)(AKV + (t % 3) * KVSTG) * 2;

        // ---- S = Q.K^T ----
        float s[8][4];
#pragma unroll
        for (int nt = 0; nt < 8; nt++)
#pragma unroll
            for (int q = 0; q < 4; q++) s[nt][q] = 0.f;
#pragma unroll
        for (int ks = 0; ks < 4; ks++) {
            int arow = wm * 16 + (lane & 15);
            int acol = ks * 16 + (lane >> 4) * 8;
            uint32_t aa = sb + (uint32_t)(AQH + arow * AT_STR + acol) * 2;
            uint32_t ah[4], al[4];
            ldsm4(ah[0], ah[1], ah[2], ah[3], aa);
            ldsm4(al[0], al[1], al[2], al[3], aa + AQL * 2);
            uint32_t bh[8][2], bl[8][2];
#pragma unroll
            for (int ng = 0; ng < 4; ng++) {
                int brow = ng * 16 + (lane & 7) + ((lane & 16) >> 1);
                int bcol = ks * 16 + ((lane >> 3) & 1) * 8;
                uint32_t ba = kb + (uint32_t)(brow * AT_STR + bcol) * 2;
                ldsm4(bh[2 * ng][0], bh[2 * ng][1], bh[2 * ng + 1][0],
                      bh[2 * ng + 1][1], ba);
                ldsm4(bl[2 * ng][0], bl[2 * ng][1], bl[2 * ng + 1][0],
                      bl[2 * ng + 1][1], ba + 4608 * 2);
            }
#pragma unroll
            for (int nt = 0; nt < 8; nt++) {
                mma16816(s[nt], ah, bh[nt]);
                mma16816(s[nt], ah, bl[nt]);
                mma16816(s[nt], al, bh[nt]);
            }
        }

        // ---- bias + exp + rowsum + attn store ----
#pragma unroll
        for (int nt = 0; nt < 8; nt++) {
            int col = k0g + nt * 8 + ((lane & 3) << 1);
            int d0 = row_q - col;     if (d0 < 0) d0 = -d0;
            int d1 = row_q - col - 1; if (d1 < 0) d1 = -d1;
            int d2 = row_q + 8 - col;     if (d2 < 0) d2 = -d2;
            int d3 = row_q + 8 - col - 1; if (d3 < 0) d3 = -d3;
            float e0 = __expf(fmaf(s[nt][0], scale, rc[d0]));
            float e1 = __expf(fmaf(s[nt][1], scale, rc[d1]));
            float e2 = __expf(fmaf(s[nt][2], scale, rc[d2]));
            float e3 = __expf(fmaf(s[nt][3], scale, rc[d3]));
            s[nt][0] = e0; s[nt][1] = e1; s[nt][2] = e2; s[nt][3] = e3;
            rs0 += e0 + e1;
            rs1 += e2 + e3;
            if (write_attn) {
                float* ap = attn + ((size_t)bh_i * N_ + row_q) * N_ + col;
                *(float2*)ap = make_float2(e0, e1);
                *(float2*)(ap + 8 * N_) = make_float2(e2, e3);
            }
        }

        // ---- O += e.V ----
        uint32_t vb0 = kb + 2 * 4608 * 2;
#pragma unroll
        for (int ks = 0; ks < 4; ks++) {
            uint32_t eah[4], eal[4];
            {
                float c0 = s[2 * ks][0], c1 = s[2 * ks][1];
                float c2 = s[2 * ks][2], c3 = s[2 * ks][3];
                float c4 = s[2 * ks + 1][0], c5 = s[2 * ks + 1][1];
                float c6 = s[2 * ks + 1][2], c7 = s[2 * ks + 1][3];
                eah[0] = pkbf(c0, c1); eah[1] = pkbf(c2, c3);
                eah[2] = pkbf(c4, c5); eah[3] = pkbf(c6, c7);
                float hh;
                hh = __bfloat162float(__float2bfloat16(c0)); c0 -= hh;
                hh = __bfloat162float(__float2bfloat16(c1)); c1 -= hh;
                hh = __bfloat162float(__float2bfloat16(c2)); c2 -= hh;
                hh = __bfloat162float(__float2bfloat16(c3)); c3 -= hh;
                hh = __bfloat162float(__float2bfloat16(c4)); c4 -= hh;
                hh = __bfloat162float(__float2bfloat16(c5)); c5 -= hh;
                hh = __bfloat162float(__float2bfloat16(c6)); c6 -= hh;
                hh = __bfloat162float(__float2bfloat16(c7)); c7 -= hh;
                eal[0] = pkbf(c0, c1); eal[1] = pkbf(c2, c3);
                eal[2] = pkbf(c4, c5); eal[3] = pkbf(c6, c7);
            }
            uint32_t vbh[8][2], vbl[8][2];
#pragma unroll
            for (int ng = 0; ng < 4; ng++) {
                int brow = ng * 16 + (lane & 7) + ((lane & 16) >> 1);
                int bcol = ks * 16 + ((lane >> 3) & 1) * 8;
                uint32_t ba = vb0 + (uint32_t)(brow * AT_STR + bcol) * 2;
                ldsm4(vbh[2 * ng][0], vbh[2 * ng][1], vbh[2 * ng + 1][0],
                      vbh[2 * ng + 1][1], ba);
                ldsm4(vbl[2 * ng][0], vbl[2 * ng][1], vbl[2 * ng + 1][0],
                      vbl[2 * ng + 1][1], ba + 4608 * 2);
            }
#pragma unroll
            for (int nh = 0; nh < 8; nh++) {
                mma16816(co[nh], eah, vbh[nh]);
                mma16816(co[nh], eah, vbl[nh]);
                mma16816(co[nh], eal, vbh[nh]);
            }
        }

        if (t + 2 < N_ / 64) issue_kv(t + 2);
    }

    // ---- rowsum reduce over quad lanes ----
    rs0 += __shfl_xor_sync(0xffffffffu, rs0, 1);
    rs0 += __shfl_xor_sync(0xffffffffu, rs0, 2);
    rs1 += __shfl_xor_sync(0xffffffffu, rs1, 1);
    rs1 += __shfl_xor_sync(0xffffffffu, rs1, 2);
    if ((lane & 3) == 0) {
        g_rowsum[(size_t)bh_i * N_ + row_q] = rs0;
        g_rowsum[(size_t)bh_i * N_ + row_q + 8] = rs1;
    }

    // ---- normalized output -> split-bf16 aoh/aol [b, row, h*64+hd] ----
    float inv0 = 1.0f / rs0, inv1 = 1.0f / rs1;
#pragma unroll
    for (int nh = 0; nh < 8; nh++) {
        int hd = nh * 8 + ((lane & 3) << 1);
        size_t p = ((size_t)(b * N_ + row_q)) * D_ + h * HD_ + hd;
        split_st2(g_aoh, g_aol, p, make_float2(co[nh][0] * inv0, co[nh][1] * inv0));
        split_st2(g_aoh, g_aol, p + 8 * D_,
                  make_float2(co[nh][2] * inv1, co[nh][3] * inv1));
    }
}

// =============================================================================
__global__ void __launch_bounds__(256) norm_kernel(float* __restrict__ attn) {
    size_t i = (size_t)blockIdx.x * 256 + threadIdx.x;
    const size_t total = (size_t)BH_ * N_ * N_ / 4;
    if (i >= total) return;
    size_t e0 = i << 2;
    int row = (int)(e0 >> 11);
    float inv = 1.0f / g_rowsum[row];
    float4 v = __ldcs((const float4*)attn + i);
    v.x *= inv; v.y *= inv; v.z *= inv; v.w *= inv;
    __stcs((float4*)attn + i, v);
}

// =============================================================================
extern "C" void kernel_launch(void* const* d_in, const int* in_sizes, int n_in,
                              void* d_out, int out_size) {
    const float* query = (const float*)d_in[0];
    const float* w_in  = (const float*)d_in[4];
    const float* b_in  = (const float*)d_in[5];
    const float* w_out = (const float*)d_in[6];
    const float* b_out = (const float*)d_in[7];
    const float* rpe   = (const float*)d_in[8];

    float* out  = (float*)d_out;
    const long long out_elems  = (long long)B_ * N_ * D_;
    const long long attn_elems = (long long)BH_ * N_ * N_;
    int write_attn = ((long long)out_size >= out_elems + attn_elems) ? 1 : 0;
    float* attn = out + out_elems;

    cudaFuncSetAttribute(attn_kernel, cudaFuncAttributeMaxDynamicSharedMemorySize,
                         ATTN_SMEM);
    cudaFuncSetAttribute(mma_gemm<true>, cudaFuncAttributeMaxDynamicSharedMemorySize,
                         GEMM_SMEM);
    cudaFuncSetAttribute(mma_gemm<false>, cudaFuncAttributeMaxDynamicSharedMemorySize,
                         GEMM_SMEM);

    __nv_bfloat16 *xh, *xl, *wih, *wil, *aoh, *aol, *woh, *wol;
    cudaGetSymbolAddress((void**)&xh,  g_xh);
    cudaGetSymbolAddress((void**)&xl,  g_xl);
    cudaGetSymbolAddress((void**)&wih, g_wih);
    cudaGetSymbolAddress((void**)&wil, g_wil);
    cudaGetSymbolAddress((void**)&aoh, g_aoh);
    cudaGetSymbolAddress((void**)&aol, g_aol);
    cudaGetSymbolAddress((void**)&woh, g_woh);
    cudaGetSymbolAddress((void**)&wol, g_wol);

    cvt_kernel<<<4096, 256>>>(query, xh, xl, 4096 * 1024 / 4);
    cvt_kernel<<<3072, 256>>>(w_in, wih, wil, 3072 * 1024 / 4);
    cvt_kernel<<<1024, 256>>>(w_out, woh, wol, 1024 * 1024 / 4);

    mma_gemm<true><<<dim3(24, 32), 256, GEMM_SMEM>>>(xh, xl, wih, wil, b_in, nullptr);

    attn_kernel<<<dim3(16, 16, 2), 256, ATTN_SMEM>>>(attn, rpe, write_attn);
    if (write_attn) {
        const int total_f4 = (int)((long long)BH_ * N_ * N_ / 4);
        norm_kernel<<<(total_f4 + 255) / 256, 256>>>(attn);
    }

    mma_gemm<false><<<dim3(8, 32), 256, GEMM_SMEM>>>(aoh, aol, woh, wol, b_out, out);
}